// round 7
// baseline (speedup 1.0000x reference)
#include <cuda_runtime.h>
#include <math.h>
#include <stdint.h>

// ---------------------------------------------------------------------------
// LSTM autoencoder: B=64, T=512, F=256, H=1024
//   init -> dummy(ncu align) -> gemm(Xe) -> enc scan -> gemm(Xd)
//        -> dec scan -> gemm(out)            (7 graph nodes)
// R6: scan at 512 threads/CTA (4 warps/SMSP, was 2) so LDS latency / sync
//     skew is hidden by warp parallelism instead of stalling the FFMA pipe.
//     Dummy kernel shifts ncu's -s 5 capture onto the decoder scan.
// ---------------------------------------------------------------------------

#define TSTEPS 512
#define BATCH  64
#define FDIM   256
#define HDIM   1024
#define G4     4096
#define NCTA_SCAN 128
#define SCAN_THREADS 512

#define HP     36            // h tile row stride (floats)
#define HTILE  (64 * HP)     // floats per chunk buffer (2304)
#define NBUF   4             // pipeline depth

// Scratch in device globals (no allocation allowed).
__device__ float g_Xe  [134217728]; // [512][64][4096]
__device__ float g_Xd  [134217728]; // [512][64][4096]
__device__ float g_ench[33554432];  // [512][64][1024]
__device__ float g_dech[33554432];  // [512][64][1024]
__device__ float g_c   [BATCH * HDIM];
__device__ float g_h0  [BATCH * HDIM];
__device__ unsigned g_bar_gen;
__device__ unsigned g_bar_cnt;

__global__ void init_state_kernel() {
    int i = blockIdx.x * blockDim.x + threadIdx.x;
    if (i < BATCH * HDIM) { g_c[i] = 0.0f; g_h0[i] = 0.0f; }
    if (i == 0) { g_bar_gen = 0u; g_bar_cnt = 0u; }
}

// No-op: shifts ncu's skip-5 capture window onto the decoder scan.
__global__ void dummy_kernel() {}

// Sense-reversal grid barrier across the 128 co-resident scan CTAs.
__device__ __forceinline__ void grid_barrier() {
    __syncthreads();
    if (threadIdx.x == 0) {
        unsigned e = *(volatile unsigned*)&g_bar_gen;
        __threadfence();                       // release my CTA's writes
        unsigned a = atomicAdd(&g_bar_cnt, 1u);
        if (a == NCTA_SCAN - 1) {
            atomicExch(&g_bar_cnt, 0u);
            __threadfence();
            *(volatile unsigned*)&g_bar_gen = e + 1u;
        } else {
            while (*(volatile unsigned*)&g_bar_gen == e) { }
            __threadfence();                   // acquire
        }
    }
    __syncthreads();
}

__device__ __forceinline__ float sigmoidf_fast(float x) {
    return 1.0f / (1.0f + __expf(-x));
}

__device__ __forceinline__ void cp16(uint32_t dst, const float* src) {
    asm volatile("cp.async.cg.shared.global [%0], [%1], 16;"
                 :: "r"(dst), "l"(src));
}
__device__ __forceinline__ void cp_commit() {
    asm volatile("cp.async.commit_group;");
}
__device__ __forceinline__ void cp_wait2() {
    asm volatile("cp.async.wait_group 2;");
}
__device__ __forceinline__ void cp_wait0() {
    asm volatile("cp.async.wait_group 0;");
}

// ---------------------------------------------------------------------------
// fp32 GEMM + bias (total gemm time ~35us; not the lever).
// ---------------------------------------------------------------------------
__global__ void __launch_bounds__(256) gemm128_kernel(
    const float* __restrict__ A, const float* __restrict__ W,
    const float* __restrict__ bias, float* __restrict__ C,
    int K, int a_sb, int a_st, int c_sb, int c_st)
{
    __shared__ __align__(16) float As[8][132];
    __shared__ __align__(16) float Bs[8][132];

    const int m0t = blockIdx.y * 128;
    const int n0t = blockIdx.x * 128;
    const int tid = threadIdx.x;
    const int lm  = tid >> 1;
    const int lk  = (tid & 1) * 4;
    const int mb  = (tid >> 4) * 8;
    const int nb  = (tid & 15) * 8;

    const int am = m0t + lm;
    const size_t aoff = (size_t)(am & 63) * a_sb + (size_t)(am >> 6) * a_st;
    const float* arow = A + aoff + lk;
    const float* wrow = W + (size_t)(n0t + lm) * K + lk;

    float acc[8][8] = {};
    float4 av = *(const float4*)(arow);
    float4 bv = *(const float4*)(wrow);

    const int nchunks = K >> 3;
    for (int ch = 0; ch < nchunks; ch++) {
        __syncthreads();
        As[lk + 0][lm] = av.x; As[lk + 1][lm] = av.y;
        As[lk + 2][lm] = av.z; As[lk + 3][lm] = av.w;
        Bs[lk + 0][lm] = bv.x; Bs[lk + 1][lm] = bv.y;
        Bs[lk + 2][lm] = bv.z; Bs[lk + 3][lm] = bv.w;
        __syncthreads();
        if (ch + 1 < nchunks) {
            av = *(const float4*)(arow + (ch + 1) * 8);
            bv = *(const float4*)(wrow + (ch + 1) * 8);
        }
#pragma unroll
        for (int q = 0; q < 8; q++) {
            float4 a0 = *(const float4*)&As[q][mb];
            float4 a1 = *(const float4*)&As[q][mb + 4];
            float4 b0 = *(const float4*)&Bs[q][nb];
            float4 b1 = *(const float4*)&Bs[q][nb + 4];
            float ar[8] = {a0.x, a0.y, a0.z, a0.w, a1.x, a1.y, a1.z, a1.w};
            float br[8] = {b0.x, b0.y, b0.z, b0.w, b1.x, b1.y, b1.z, b1.w};
#pragma unroll
            for (int r = 0; r < 8; r++)
#pragma unroll
                for (int c = 0; c < 8; c++)
                    acc[r][c] += ar[r] * br[c];
        }
    }

    float4 bi0 = *(const float4*)(bias + n0t + nb);
    float4 bi1 = *(const float4*)(bias + n0t + nb + 4);
    const float bb[8] = {bi0.x, bi0.y, bi0.z, bi0.w, bi1.x, bi1.y, bi1.z, bi1.w};

#pragma unroll
    for (int r = 0; r < 8; r++) {
        int m = m0t + mb + r;
        size_t cbase = (size_t)(m & 63) * c_sb + (size_t)(m >> 6) * c_st
                     + n0t + nb;
        float4 o0 = make_float4(acc[r][0] + bb[0], acc[r][1] + bb[1],
                                acc[r][2] + bb[2], acc[r][3] + bb[3]);
        float4 o1 = make_float4(acc[r][4] + bb[4], acc[r][5] + bb[5],
                                acc[r][6] + bb[6], acc[r][7] + bb[7]);
        *(float4*)(C + cbase)     = o0;
        *(float4*)(C + cbase + 4) = o1;
    }
}

// ---------------------------------------------------------------------------
// Persistent LSTM scan: 512 threads (16 warps, 4/SMSP).
// CTA j owns h cols [j*8, j*8+8). Thread: row m = tid>>3 (0..63), col
// cj = tid&7; computes the (i,f,g,o) quadruple for (m, jc0+cj).
// Weights gate-interleaved in smem: Ws[k*36 + cj*4 + gate] (one LDS.128).
// h chunks (32 k) staged [m][k] via cp.async 4-deep ring, 1 seg/thread.
// Activations & cell state fully register-resident.
// smem: Ws 147456B + 4 x 64x36 h tiles 36864B = 184320B -> 1 CTA/SM.
// ---------------------------------------------------------------------------
__global__ void __launch_bounds__(SCAN_THREADS) lstm_scan_kernel(
    const float* __restrict__ Hin0,     // [64][1024] initial h
    const float* __restrict__ Xp_base,  // [512][64][4096] input-part (+bias)
    const float* __restrict__ Whh,      // [4096][1024]
    float* __restrict__ cbuf,           // [64][1024] c seed in / c_T out
    float* __restrict__ Hser)           // [512][64][1024] per-step h out
{
    extern __shared__ float sm[];
    float* Ws = sm;                     // [1024][36]
    float* Hs = sm + 36864;             // NBUF x HTILE

    const int j   = blockIdx.x;
    const int jc0 = j * 8;
    const int tid = threadIdx.x;

    const uint32_t hs_u32 = (uint32_t)__cvta_generic_to_shared(Hs);

    // one-time: Whh slice -> smem, gate-interleaved: Ws[k][cj*4+gate]
    {
        int c  = tid >> 4;              // 0..31
        int cj = c >> 2;                // 0..7
        int g  = c & 3;                 // i/f/g/o
        const float* wr = Whh + (size_t)(g * HDIM + jc0 + cj) * HDIM;
        for (int k0 = (tid & 15) * 4; k0 < HDIM; k0 += 64) {
            float4 w = *(const float4*)(wr + k0);
            Ws[(k0 + 0) * 36 + c] = w.x;
            Ws[(k0 + 1) * 36 + c] = w.y;
            Ws[(k0 + 2) * 36 + c] = w.z;
            Ws[(k0 + 3) * 36 + c] = w.w;
        }
    }

    const int m     = tid >> 3;         // 0..63
    const int cj    = tid & 7;
    const int gbase = jc0 + cj;

    // per-thread copy assignment: 1 x 16B segment (512 segs = 64 rows x 8)
    const int r0 = tid >> 3;            // row
    const int s0 = tid & 7;             // 16B segment within 32-float chunk

    // cell state in a register for the whole scan
    float cr = cbuf[m * HDIM + gbase];

    const float* Hin = Hin0;
    for (int t = 0; t < TSTEPS; t++) {
        const float* Xp   = Xp_base + (size_t)t * (BATCH * G4);
        float*       Hout = Hser    + (size_t)t * (BATCH * HDIM);

        // prefetch Xp early (consumed ~20us later)
        const float* xr = Xp + (size_t)m * G4 + gbase;
        float xi = xr[0], xf = xr[1024], xg = xr[2048], xo = xr[3072];

        // prologue: issue chunks 0..2
#pragma unroll
        for (int p = 0; p < 3; p++) {
            uint32_t hb = hs_u32 + (uint32_t)((p & 3) * HTILE) * 4u;
            cp16(hb + (uint32_t)(r0 * HP + s0 * 4) * 4u,
                 Hin + r0 * HDIM + p * 32 + s0 * 4);
            cp_commit();
        }

        float ai = 0.f, af = 0.f, ag = 0.f, ao = 0.f;

        for (int ch = 0; ch < 32; ch++) {
            cp_wait2();                  // chunk ch complete (this thread)
            __syncthreads();             // ... and every thread's part
            {                            // issue chunk ch+3 (or empty group)
                int nc = ch + 3;
                if (nc < 32) {
                    uint32_t hb = hs_u32 + (uint32_t)((nc & 3) * HTILE) * 4u;
                    cp16(hb + (uint32_t)(r0 * HP + s0 * 4) * 4u,
                         Hin + r0 * HDIM + nc * 32 + s0 * 4);
                }
                cp_commit();             // empty groups keep wait_group 2 valid
            }

            const float* hb = Hs + (ch & 3) * HTILE + m * HP;
            const float* wp = Ws + (ch * 32) * 36 + cj * 4;
#pragma unroll
            for (int kc = 0; kc < 32; kc++) {
                float  h = hb[kc];
                float4 w = *(const float4*)(wp + kc * 36);
                ai += h * w.x; af += h * w.y;
                ag += h * w.z; ao += h * w.w;
            }
        }
        cp_wait0();                      // drain empty groups before reuse

        // activations fully in registers
        float gi = ai + xi, gf = af + xf, gg = ag + xg, go = ao + xo;
        float ii = sigmoidf_fast(gi), ff = sigmoidf_fast(gf);
        float oo = sigmoidf_fast(go), tg = tanhf(gg);

        cr = ff * cr + ii * tg;
        Hout[m * HDIM + gbase] = oo * tanhf(cr);

        grid_barrier();                  // publish Hout for step t+1
        Hin = Hout;
    }

    // hand c off (encoder c_T seeds the decoder)
    cbuf[m * HDIM + gbase] = cr;
}

// ---------------------------------------------------------------------------
extern "C" void kernel_launch(void* const* d_in, const int* in_sizes, int n_in,
                              void* d_out, int out_size)
{
    const float* x      = (const float*)d_in[0]; // [64,512,256]
    const float* W_ih_e = (const float*)d_in[1]; // [4096,256]
    const float* W_hh_e = (const float*)d_in[2]; // [4096,1024]
    const float* b_e    = (const float*)d_in[3]; // [4096]
    const float* W_ih_d = (const float*)d_in[4]; // [4096,1024]
    const float* W_hh_d = (const float*)d_in[5]; // [4096,1024]
    const float* b_d    = (const float*)d_in[6]; // [4096]
    const float* W_out  = (const float*)d_in[7]; // [256,1024]
    const float* b_out  = (const float*)d_in[8]; // [256]
    float* out = (float*)d_out;                  // [64,512,256]

    float *Xe, *Xd, *ench, *dech, *cbuf, *h0;
    cudaGetSymbolAddress((void**)&Xe,   g_Xe);
    cudaGetSymbolAddress((void**)&Xd,   g_Xd);
    cudaGetSymbolAddress((void**)&ench, g_ench);
    cudaGetSymbolAddress((void**)&dech, g_dech);
    cudaGetSymbolAddress((void**)&cbuf, g_c);
    cudaGetSymbolAddress((void**)&h0,   g_h0);

    const int SCAN_SMEM = (36864 + NBUF * HTILE) * 4;   // 184320 bytes
    cudaFuncSetAttribute(lstm_scan_kernel,
                         cudaFuncAttributeMaxDynamicSharedMemorySize, SCAN_SMEM);

    // reset h0/c/barrier state (deterministic across graph replays)
    init_state_kernel<<<256, 256>>>();

    // ncu alignment: makes the decoder scan the 6th launch (ncu -s 5 -c 1)
    dummy_kernel<<<1, 32>>>();

    // Xe[t,b,:] = x[b,t,:] @ W_ih_e^T + b_e   (m = t*64+b)
    gemm128_kernel<<<dim3(G4 / 128, (TSTEPS * BATCH) / 128), 256>>>(
        x, W_ih_e, b_e, Xe, FDIM, 131072, 256, 4096, 262144);

    // encoder scan (persistent, 512 steps)
    lstm_scan_kernel<<<NCTA_SCAN, SCAN_THREADS, SCAN_SMEM>>>(
        h0, Xe, W_hh_e, cbuf, ench);

    // Xd = enc_hs @ W_ih_d^T + b_d   (enc_hs is [t][b][h])
    gemm128_kernel<<<dim3(G4 / 128, (TSTEPS * BATCH) / 128), 256>>>(
        ench, W_ih_d, b_d, Xd, HDIM, 1024, 65536, 4096, 262144);

    // decoder scan: seeded by enc_hs[511] (= h_T) and cbuf (= c_T)
    lstm_scan_kernel<<<NCTA_SCAN, SCAN_THREADS, SCAN_SMEM>>>(
        ench + (size_t)(TSTEPS - 1) * (BATCH * HDIM), Xd, W_hh_d, cbuf, dech);

    // out[b,t,:] = dec_hs[t,b,:] @ W_out^T + b_out
    gemm128_kernel<<<dim3(FDIM / 128, (TSTEPS * BATCH) / 128), 256>>>(
        dech, W_out, b_out, out, HDIM, 1024, 65536, 131072, 256);
}

// round 8
// speedup vs baseline: 1.4979x; 1.4979x over previous
#include <cuda_runtime.h>
#include <math.h>
#include <stdint.h>

// ---------------------------------------------------------------------------
// LSTM autoencoder: B=64, T=512, F=256, H=1024
//   init -> dummy(ncu align) -> gemm(Xe) -> enc scan -> gemmT(Xd)
//        -> dec scan -> gemmT(out)            (7 graph nodes)
// R7: scan back to 256 threads (R6's 512-thread variant was LSU-bound:
//     fma=16.6%, L1=73%). h time-series stored TRANSPOSED [t][k][m] so the
//     inner loop is 8 FFMA : 2 LDS (one LDS.128 weights + one LDS.64 h pair)
//     and cp.async staging is a flat contiguous 8KB chunk copy.
// ---------------------------------------------------------------------------

#define TSTEPS 512
#define BATCH  64
#define FDIM   256
#define HDIM   1024
#define G4     4096
#define NCTA_SCAN 128

#define HCH    2048          // floats per h chunk: 32 k x 64 m (8KB)
#define NBUF   4             // pipeline depth

// Scratch in device globals (no allocation allowed).
__device__ float g_Xe  [134217728]; // [512][64][4096]   (t, b, gatecol)
__device__ float g_Xd  [134217728]; // [512][64][4096]
__device__ float g_ench[33554432];  // [512][1024][64]   TRANSPOSED (t, k, m)
__device__ float g_dech[33554432];  // [512][1024][64]   TRANSPOSED
__device__ float g_c   [BATCH * HDIM];
__device__ float g_h0  [HDIM * BATCH];   // zeros (layout-independent)
__device__ unsigned g_bar_gen;
__device__ unsigned g_bar_cnt;

__global__ void init_state_kernel() {
    int i = blockIdx.x * blockDim.x + threadIdx.x;
    if (i < BATCH * HDIM) { g_c[i] = 0.0f; g_h0[i] = 0.0f; }
    if (i == 0) { g_bar_gen = 0u; g_bar_cnt = 0u; }
}

// No-op: shifts ncu's skip-5 capture window onto the decoder scan.
__global__ void dummy_kernel() {}

// Sense-reversal grid barrier across the 128 co-resident scan CTAs.
__device__ __forceinline__ void grid_barrier() {
    __syncthreads();
    if (threadIdx.x == 0) {
        unsigned e = *(volatile unsigned*)&g_bar_gen;
        __threadfence();                       // release my CTA's writes
        unsigned a = atomicAdd(&g_bar_cnt, 1u);
        if (a == NCTA_SCAN - 1) {
            atomicExch(&g_bar_cnt, 0u);
            __threadfence();
            *(volatile unsigned*)&g_bar_gen = e + 1u;
        } else {
            while (*(volatile unsigned*)&g_bar_gen == e) { }
            __threadfence();                   // acquire
        }
    }
    __syncthreads();
}

__device__ __forceinline__ float sigmoidf_fast(float x) {
    return 1.0f / (1.0f + __expf(-x));
}

__device__ __forceinline__ void cp16(uint32_t dst, const float* src) {
    asm volatile("cp.async.cg.shared.global [%0], [%1], 16;"
                 :: "r"(dst), "l"(src));
}
__device__ __forceinline__ void cp_commit() {
    asm volatile("cp.async.commit_group;");
}
__device__ __forceinline__ void cp_wait2() {
    asm volatile("cp.async.wait_group 2;");
}
__device__ __forceinline__ void cp_wait0() {
    asm volatile("cp.async.wait_group 0;");
}

// ---------------------------------------------------------------------------
// fp32 GEMM + bias, A k-contiguous (used for the Xe projection).
//   C[coff(m)+n] = bias[n] + sum_k A[aoff(m)+k] * W[n*K+k]
// ---------------------------------------------------------------------------
__global__ void __launch_bounds__(256) gemm128_kernel(
    const float* __restrict__ A, const float* __restrict__ W,
    const float* __restrict__ bias, float* __restrict__ C,
    int K, int a_sb, int a_st, int c_sb, int c_st)
{
    __shared__ __align__(16) float As[8][132];
    __shared__ __align__(16) float Bs[8][132];

    const int m0t = blockIdx.y * 128;
    const int n0t = blockIdx.x * 128;
    const int tid = threadIdx.x;
    const int lm  = tid >> 1;
    const int lk  = (tid & 1) * 4;
    const int mb  = (tid >> 4) * 8;
    const int nb  = (tid & 15) * 8;

    const int am = m0t + lm;
    const size_t aoff = (size_t)(am & 63) * a_sb + (size_t)(am >> 6) * a_st;
    const float* arow = A + aoff + lk;
    const float* wrow = W + (size_t)(n0t + lm) * K + lk;

    float acc[8][8] = {};
    float4 av = *(const float4*)(arow);
    float4 bv = *(const float4*)(wrow);

    const int nchunks = K >> 3;
    for (int ch = 0; ch < nchunks; ch++) {
        __syncthreads();
        As[lk + 0][lm] = av.x; As[lk + 1][lm] = av.y;
        As[lk + 2][lm] = av.z; As[lk + 3][lm] = av.w;
        Bs[lk + 0][lm] = bv.x; Bs[lk + 1][lm] = bv.y;
        Bs[lk + 2][lm] = bv.z; Bs[lk + 3][lm] = bv.w;
        __syncthreads();
        if (ch + 1 < nchunks) {
            av = *(const float4*)(arow + (ch + 1) * 8);
            bv = *(const float4*)(wrow + (ch + 1) * 8);
        }
#pragma unroll
        for (int q = 0; q < 8; q++) {
            float4 a0 = *(const float4*)&As[q][mb];
            float4 a1 = *(const float4*)&As[q][mb + 4];
            float4 b0 = *(const float4*)&Bs[q][nb];
            float4 b1 = *(const float4*)&Bs[q][nb + 4];
            float ar[8] = {a0.x, a0.y, a0.z, a0.w, a1.x, a1.y, a1.z, a1.w};
            float br[8] = {b0.x, b0.y, b0.z, b0.w, b1.x, b1.y, b1.z, b1.w};
#pragma unroll
            for (int r = 0; r < 8; r++)
#pragma unroll
                for (int c = 0; c < 8; c++)
                    acc[r][c] += ar[r] * br[c];
        }
    }

    float4 bi0 = *(const float4*)(bias + n0t + nb);
    float4 bi1 = *(const float4*)(bias + n0t + nb + 4);
    const float bb[8] = {bi0.x, bi0.y, bi0.z, bi0.w, bi1.x, bi1.y, bi1.z, bi1.w};

#pragma unroll
    for (int r = 0; r < 8; r++) {
        int m = m0t + mb + r;
        size_t cbase = (size_t)(m & 63) * c_sb + (size_t)(m >> 6) * c_st
                     + n0t + nb;
        float4 o0 = make_float4(acc[r][0] + bb[0], acc[r][1] + bb[1],
                                acc[r][2] + bb[2], acc[r][3] + bb[3]);
        float4 o1 = make_float4(acc[r][4] + bb[4], acc[r][5] + bb[5],
                                acc[r][6] + bb[6], acc[r][7] + bb[7]);
        *(float4*)(C + cbase)     = o0;
        *(float4*)(C + cbase + 4) = o1;
    }
}

// ---------------------------------------------------------------------------
// Variant: A stored k-strided (transposed h series [t][k][m], k-stride 64).
//   A element (m, k) at aoff(m) + k*64 ; aoff(m) = (m&63)*a_sb + (m>>6)*a_st
// ---------------------------------------------------------------------------
__global__ void __launch_bounds__(256) gemm128T_kernel(
    const float* __restrict__ A, const float* __restrict__ W,
    const float* __restrict__ bias, float* __restrict__ C,
    int K, int a_sb, int a_st, int c_sb, int c_st)
{
    __shared__ __align__(16) float As[8][132];
    __shared__ __align__(16) float Bs[8][132];

    const int m0t = blockIdx.y * 128;
    const int n0t = blockIdx.x * 128;
    const int tid = threadIdx.x;
    const int lm  = tid >> 1;
    const int lk  = (tid & 1) * 4;
    const int mb  = (tid >> 4) * 8;
    const int nb  = (tid & 15) * 8;

    const int am = m0t + lm;
    const size_t aoff = (size_t)(am & 63) * a_sb + (size_t)(am >> 6) * a_st;
    const float* arow = A + aoff;                 // k scaled by 64
    const float* wrow = W + (size_t)(n0t + lm) * K + lk;

    float acc[8][8] = {};
    float a0 = arow[(size_t)(lk + 0) * 64];
    float a1 = arow[(size_t)(lk + 1) * 64];
    float a2 = arow[(size_t)(lk + 2) * 64];
    float a3 = arow[(size_t)(lk + 3) * 64];
    float4 bv = *(const float4*)(wrow);

    const int nchunks = K >> 3;
    for (int ch = 0; ch < nchunks; ch++) {
        __syncthreads();
        As[lk + 0][lm] = a0; As[lk + 1][lm] = a1;
        As[lk + 2][lm] = a2; As[lk + 3][lm] = a3;
        Bs[lk + 0][lm] = bv.x; Bs[lk + 1][lm] = bv.y;
        Bs[lk + 2][lm] = bv.z; Bs[lk + 3][lm] = bv.w;
        __syncthreads();
        if (ch + 1 < nchunks) {
            const float* ap = arow + (size_t)((ch + 1) * 8 + lk) * 64;
            a0 = ap[0]; a1 = ap[64]; a2 = ap[128]; a3 = ap[192];
            bv = *(const float4*)(wrow + (ch + 1) * 8);
        }
#pragma unroll
        for (int q = 0; q < 8; q++) {
            float4 x0 = *(const float4*)&As[q][mb];
            float4 x1 = *(const float4*)&As[q][mb + 4];
            float4 b0 = *(const float4*)&Bs[q][nb];
            float4 b1 = *(const float4*)&Bs[q][nb + 4];
            float ar[8] = {x0.x, x0.y, x0.z, x0.w, x1.x, x1.y, x1.z, x1.w};
            float br[8] = {b0.x, b0.y, b0.z, b0.w, b1.x, b1.y, b1.z, b1.w};
#pragma unroll
            for (int r = 0; r < 8; r++)
#pragma unroll
                for (int c = 0; c < 8; c++)
                    acc[r][c] += ar[r] * br[c];
        }
    }

    float4 bi0 = *(const float4*)(bias + n0t + nb);
    float4 bi1 = *(const float4*)(bias + n0t + nb + 4);
    const float bb[8] = {bi0.x, bi0.y, bi0.z, bi0.w, bi1.x, bi1.y, bi1.z, bi1.w};

#pragma unroll
    for (int r = 0; r < 8; r++) {
        int m = m0t + mb + r;
        size_t cbase = (size_t)(m & 63) * c_sb + (size_t)(m >> 6) * c_st
                     + n0t + nb;
        float4 o0 = make_float4(acc[r][0] + bb[0], acc[r][1] + bb[1],
                                acc[r][2] + bb[2], acc[r][3] + bb[3]);
        float4 o1 = make_float4(acc[r][4] + bb[4], acc[r][5] + bb[5],
                                acc[r][6] + bb[6], acc[r][7] + bb[7]);
        *(float4*)(C + cbase)     = o0;
        *(float4*)(C + cbase + 4) = o1;
    }
}

// ---------------------------------------------------------------------------
// Persistent LSTM scan: 256 threads, transposed h series [t][k][m].
// CTA j owns h cols [j*8, j*8+8). Thread: rows m0, m0+1 (m0=(tid>>3)*2),
// col cj = tid&7 -> computes (i,f,g,o) for both rows.
// Weights gate-interleaved: Ws[k*36 + cj*4 + gate] (one LDS.128, broadcast).
// h chunk [32 k][64 m] contiguous 8KB, cp.async 4-deep ring, 2 seg/thread.
// Inner kc: 1 LDS.128 (w) + 1 LDS.64 (h pair) + 8 FFMA.
// smem: Ws 147456B + 4 x 8192B = 180224B -> 1 CTA/SM.
// ---------------------------------------------------------------------------
__global__ void __launch_bounds__(256) lstm_scan_kernel(
    const float* __restrict__ Hin0,     // [1024][64] initial h (transposed)
    const float* __restrict__ Xp_base,  // [512][64][4096] input-part (+bias)
    const float* __restrict__ Whh,      // [4096][1024]
    float* __restrict__ cbuf,           // [64][1024] c seed in / c_T out
    float* __restrict__ Hser)           // [512][1024][64] per-step h out (T)
{
    extern __shared__ float sm[];
    float* Ws = sm;                     // [1024][36]
    float* Hs = sm + 36864;             // NBUF x HCH  (no padding needed)

    const int j   = blockIdx.x;
    const int jc0 = j * 8;
    const int tid = threadIdx.x;

    const uint32_t hs_u32 = (uint32_t)__cvta_generic_to_shared(Hs);

    // one-time: Whh slice -> smem, gate-interleaved: Ws[k][cj*4+gate]
    {
        int c  = tid >> 3;              // 0..31
        int cj = c >> 2;                // 0..7
        int g  = c & 3;                 // i/f/g/o
        const float* wr = Whh + (size_t)(g * HDIM + jc0 + cj) * HDIM;
        for (int k0 = (tid & 7) * 4; k0 < HDIM; k0 += 32) {
            float4 w = *(const float4*)(wr + k0);
            Ws[(k0 + 0) * 36 + c] = w.x;
            Ws[(k0 + 1) * 36 + c] = w.y;
            Ws[(k0 + 2) * 36 + c] = w.z;
            Ws[(k0 + 3) * 36 + c] = w.w;
        }
    }

    const int m0    = (tid >> 3) * 2;   // 0..62
    const int cj    = tid & 7;
    const int gbase = jc0 + cj;

    // cell state in registers for the whole scan
    float c0r = cbuf[m0 * HDIM + gbase];
    float c1r = cbuf[(m0 + 1) * HDIM + gbase];

    // copy mapping: thread copies floats [tid*8, tid*8+8) of each 2048-f chunk
    const uint32_t dst0 = (uint32_t)(tid * 32);        // byte offset in chunk
    const int      src0 = tid * 8;

    const float* Hin = Hin0;
    for (int t = 0; t < TSTEPS; t++) {
        const float* Xp   = Xp_base + (size_t)t * (BATCH * G4);
        float*       Hout = Hser    + (size_t)t * (HDIM * BATCH);

        // prefetch Xp early (consumed ~20us later)
        const float* xr0 = Xp + (size_t)m0 * G4 + gbase;
        const float* xr1 = xr0 + G4;
        float xi0 = xr0[0], xf0 = xr0[1024], xg0 = xr0[2048], xo0 = xr0[3072];
        float xi1 = xr1[0], xf1 = xr1[1024], xg1 = xr1[2048], xo1 = xr1[3072];

        // prologue: issue chunks 0..2
#pragma unroll
        for (int p = 0; p < 3; p++) {
            uint32_t hb = hs_u32 + (uint32_t)(p * HCH) * 4u + dst0;
            cp16(hb,      Hin + p * HCH + src0);
            cp16(hb + 16, Hin + p * HCH + src0 + 4);
            cp_commit();
        }

        float a00 = 0.f, a01 = 0.f, a02 = 0.f, a03 = 0.f;
        float a10 = 0.f, a11 = 0.f, a12 = 0.f, a13 = 0.f;

        for (int ch = 0; ch < 32; ch++) {
            cp_wait2();                  // chunk ch complete (this thread)
            __syncthreads();             // ... and every thread's part
            {                            // issue chunk ch+3 (or empty group)
                int nc = ch + 3;
                if (nc < 32) {
                    uint32_t hb = hs_u32 + (uint32_t)((nc & 3) * HCH) * 4u + dst0;
                    cp16(hb,      Hin + nc * HCH + src0);
                    cp16(hb + 16, Hin + nc * HCH + src0 + 4);
                }
                cp_commit();             // empty groups keep wait_group 2 valid
            }

            const float* hb = Hs + (ch & 3) * HCH + m0;      // [k][m] stride 64
            const float* wp = Ws + (ch * 32) * 36 + cj * 4;
#pragma unroll
            for (int kc = 0; kc < 32; kc++) {
                float2 h = *(const float2*)(hb + kc * 64);   // rows m0, m0+1
                float4 w = *(const float4*)(wp + kc * 36);
                a00 += h.x * w.x; a01 += h.x * w.y;
                a02 += h.x * w.z; a03 += h.x * w.w;
                a10 += h.y * w.x; a11 += h.y * w.y;
                a12 += h.y * w.z; a13 += h.y * w.w;
            }
        }
        cp_wait0();                      // drain empty groups before reuse

        // activations fully in registers
        float gi0 = a00 + xi0, gf0 = a01 + xf0;
        float gg0 = a02 + xg0, go0 = a03 + xo0;
        float gi1 = a10 + xi1, gf1 = a11 + xf1;
        float gg1 = a12 + xg1, go1 = a13 + xo1;

        float ii0 = sigmoidf_fast(gi0), ff0 = sigmoidf_fast(gf0);
        float oo0 = sigmoidf_fast(go0), tg0 = tanhf(gg0);
        float ii1 = sigmoidf_fast(gi1), ff1 = sigmoidf_fast(gf1);
        float oo1 = sigmoidf_fast(go1), tg1 = tanhf(gg1);

        c0r = ff0 * c0r + ii0 * tg0;
        c1r = ff1 * c1r + ii1 * tg1;

        // transposed store: Hout[k=gbase][m0..m0+1] as one STG.64
        *(float2*)(Hout + (size_t)gbase * BATCH + m0)
            = make_float2(oo0 * tanhf(c0r), oo1 * tanhf(c1r));

        grid_barrier();                  // publish Hout for step t+1
        Hin = Hout;
    }

    // hand c off (encoder c_T seeds the decoder)
    cbuf[m0 * HDIM + gbase]       = c0r;
    cbuf[(m0 + 1) * HDIM + gbase] = c1r;
}

// ---------------------------------------------------------------------------
extern "C" void kernel_launch(void* const* d_in, const int* in_sizes, int n_in,
                              void* d_out, int out_size)
{
    const float* x      = (const float*)d_in[0]; // [64,512,256]
    const float* W_ih_e = (const float*)d_in[1]; // [4096,256]
    const float* W_hh_e = (const float*)d_in[2]; // [4096,1024]
    const float* b_e    = (const float*)d_in[3]; // [4096]
    const float* W_ih_d = (const float*)d_in[4]; // [4096,1024]
    const float* W_hh_d = (const float*)d_in[5]; // [4096,1024]
    const float* b_d    = (const float*)d_in[6]; // [4096]
    const float* W_out  = (const float*)d_in[7]; // [256,1024]
    const float* b_out  = (const float*)d_in[8]; // [256]
    float* out = (float*)d_out;                  // [64,512,256]

    float *Xe, *Xd, *ench, *dech, *cbuf, *h0;
    cudaGetSymbolAddress((void**)&Xe,   g_Xe);
    cudaGetSymbolAddress((void**)&Xd,   g_Xd);
    cudaGetSymbolAddress((void**)&ench, g_ench);
    cudaGetSymbolAddress((void**)&dech, g_dech);
    cudaGetSymbolAddress((void**)&cbuf, g_c);
    cudaGetSymbolAddress((void**)&h0,   g_h0);

    const int SCAN_SMEM = (36864 + NBUF * HCH) * 4;   // 180224 bytes
    cudaFuncSetAttribute(lstm_scan_kernel,
                         cudaFuncAttributeMaxDynamicSharedMemorySize, SCAN_SMEM);

    // reset h0/c/barrier state (deterministic across graph replays)
    init_state_kernel<<<256, 256>>>();

    // ncu alignment: makes the decoder scan the 6th launch (ncu -s 5 -c 1)
    dummy_kernel<<<1, 32>>>();

    // Xe[t,b,:] = x[b,t,:] @ W_ih_e^T + b_e   (m = t*64+b; A k-contiguous)
    gemm128_kernel<<<dim3(G4 / 128, (TSTEPS * BATCH) / 128), 256>>>(
        x, W_ih_e, b_e, Xe, FDIM, 131072, 256, 4096, 262144);

    // encoder scan (persistent, 512 steps) — h series transposed [t][k][m]
    lstm_scan_kernel<<<NCTA_SCAN, 256, SCAN_SMEM>>>(
        h0, Xe, W_hh_e, cbuf, ench);

    // Xd[t][b][:] = enc_hs[t,:,b] @ W_ih_d^T + b_d   (A = ench_T, k-stride 64)
    gemm128T_kernel<<<dim3(G4 / 128, (TSTEPS * BATCH) / 128), 256>>>(
        ench, W_ih_d, b_d, Xd, HDIM, 1, 65536, 4096, 262144);

    // decoder scan: seeded by enc_hs[511] (transposed slice) and cbuf (= c_T)
    lstm_scan_kernel<<<NCTA_SCAN, 256, SCAN_SMEM>>>(
        ench + (size_t)(TSTEPS - 1) * (HDIM * BATCH), Xd, W_hh_d, cbuf, dech);

    // out[b,t,:] = dec_hs[t,:,b] @ W_out^T + b_out   (A = dech_T)
    gemm128T_kernel<<<dim3(FDIM / 128, (TSTEPS * BATCH) / 128), 256>>>(
        dech, W_out, b_out, out, HDIM, 1, 65536, 131072, 256);
}